// round 11
// baseline (speedup 1.0000x reference)
#include <cuda_runtime.h>
#include <math.h>

// ---------------------------------------------------------------------------
// LMU: folded single-GEMM persistent recurrence, fp32 with f32x2 FMA.
//   z = [h(1024); m(512)], per step: z' = act( Wbig @ z + x_t * bx ),
//   tanh on rows < 1024.  Wbig/bx precomputed on-device each launch:
//     wmb = W_m@BT
//     Hh  = W_h + wmb (x) e_h            Hm = W_m + W_m@AT + wmb (x) e_m
//     Mh  = BT (x) e_h                   Mm = I + AT + BT (x) e_m
//     bx  = [W_x + e_x*wmb ; e_x*BT]
//   z storage (interleaved row pairs so one LDG.128 fetches 2 rows x 2 batches):
//     zI[k2*64 + pair] = ulonglong2{ row 2k2   batches 2p..2p+1,
//                                    row 2k2+1 batches 2p..2p+1 }
// ---------------------------------------------------------------------------

#define NZ     1536
#define NH     1024
#define NO     512
#define NB     128
#define TSTEPS 784
#define NCTA   128
#define RPC    12           // rows per CTA
#define K2     768          // NZ/2 (row pairs)
#define SMEMB  (RPC * K2 * 16)   // 147456 B: dup'd f32x2 weight pairs

typedef unsigned long long ull;

__device__ float      g_W[NZ * NZ];        // folded Wbig, row-major
__device__ float      g_bx[NZ];
__device__ float      g_wmb[NH];
__device__ ulonglong2 g_z[2][K2 * 64];     // ping-pong state, interleaved
__device__ unsigned   g_bar;               // monotonic grid-barrier counter

// ---- packed fp32x2 helpers -------------------------------------------------
__device__ __forceinline__ ull pack2(float a, float b) {
    ull d; unsigned x = __float_as_uint(a), y = __float_as_uint(b);
    asm("mov.b64 %0, {%1, %2};" : "=l"(d) : "r"(x), "r"(y));
    return d;
}
__device__ __forceinline__ void unpack2(ull v, float& a, float& b) {
    unsigned x, y;
    asm("mov.b64 {%0, %1}, %2;" : "=r"(x), "=r"(y) : "l"(v));
    a = __uint_as_float(x); b = __uint_as_float(y);
}
__device__ __forceinline__ ull fma2(ull a, ull b, ull c) {
    ull d;
    asm("fma.rn.f32x2 %0, %1, %2, %3;" : "=l"(d) : "l"(a), "l"(b), "l"(c));
    return d;
}
__device__ __forceinline__ ulonglong2 ldcg2(const ulonglong2* p) {
    ulonglong2 v;
    asm volatile("ld.global.cg.v2.u64 {%0,%1}, [%2];"
                 : "=l"(v.x), "=l"(v.y) : "l"(p));
    return v;
}

// ---- prep: wmb = W_m@BT, bias bx -------------------------------------------
__global__ void prepA(const float* __restrict__ W_m, const float* __restrict__ BT,
                      const float* __restrict__ W_x, const float* __restrict__ e_x) {
    int i = blockIdx.x * blockDim.x + threadIdx.x;
    float ex = e_x[0];
    if (i < NH) {
        float s = 0.f;
        for (int j = 0; j < NO; ++j) s = fmaf(W_m[i * NO + j], BT[j], s);
        g_wmb[i] = s;
        g_bx[i]  = W_x[i] + s * ex;
    } else if (i < NZ) {
        g_bx[i] = BT[i - NH] * ex;
    }
}

// ---- prep: Hm block  g_W[i][1024+k] = (W_m@AT)[i,k] + W_m[i,k] + wmb[i]e_m[k]
__global__ void prepHm(const float* __restrict__ W_m, const float* __restrict__ AT,
                       const float* __restrict__ e_m) {
    int id = blockIdx.x * blockDim.x + threadIdx.x;   // 1024*512 threads exactly
    int i = id >> 9, k = id & 511;
    float s = 0.f;
    for (int j = 0; j < NO; ++j) s = fmaf(W_m[i * NO + j], AT[j * NO + k], s);
    g_W[i * NZ + NH + k] = s + W_m[i * NO + k] + g_wmb[i] * e_m[k];
}

// ---- prep: Hh, Mh, Mm blocks ------------------------------------------------
__global__ void prepRest(const float* __restrict__ W_h, const float* __restrict__ AT,
                         const float* __restrict__ BT, const float* __restrict__ e_h,
                         const float* __restrict__ e_m) {
    for (int id = blockIdx.x * blockDim.x + threadIdx.x; id < NZ * NZ;
         id += gridDim.x * blockDim.x) {
        int r = id / NZ, c = id - r * NZ;
        if (r < NH) {
            if (c < NH) g_W[id] = W_h[r * NH + c] + g_wmb[r] * e_h[c];
            // c >= NH written by prepHm
        } else {
            int j = r - NH;
            if (c < NH) {
                g_W[id] = BT[j] * e_h[c];
            } else {
                int k = c - NH;
                g_W[id] = ((j == k) ? 1.0f : 0.0f) + AT[j * NO + k] + BT[j] * e_m[k];
            }
        }
    }
}

// ---- prep: zero initial state + barrier counter ----------------------------
__global__ void prepInit() {
    int id = blockIdx.x * blockDim.x + threadIdx.x;   // 768*256 = NZ*NB exactly
    ((float*)g_z[0])[id] = 0.0f;
    if (id == 0) g_bar = 0u;
}

// ---- main persistent recurrence --------------------------------------------
// 128 CTAs x 256 thr, 1 CTA/SM (147KB smem => occ 1; all co-resident, so the
// monotonic-counter grid barrier is deadlock-free). CTA owns rows [cta*12,+12).
// Thread: 3 rows x 2 batches. Weights dup'd in SMEM; z ping-pongs in L2 (.cg).
__global__ void __launch_bounds__(256, 1) lmu_main(const float* __restrict__ x_in) {
    extern __shared__ ulonglong2 ws[];   // ws[r*K2+k2] = {dup(w[r][2k2]), dup(w[r][2k2+1])}
    const int tid = threadIdx.x;
    const int cta = blockIdx.x;
    const int R0  = cta * RPC;

    // stage + duplicate this CTA's weight slice
    const float2* gw2 = (const float2*)g_W;
    for (int idx = tid; idx < RPC * K2; idx += 256) {
        int r = idx / K2, k2 = idx - r * K2;
        float2 w = gw2[(size_t)(R0 + r) * K2 + k2];
        ulonglong2 v;
        v.x = pack2(w.x, w.x);
        v.y = pack2(w.y, w.y);
        ws[idx] = v;
    }

    const int pair = tid & 63;           // batches 2*pair, 2*pair+1
    const int rg   = tid >> 6;           // 0..3, uniform within each warp
    const int r0   = R0 + rg * 3;

    const ull bxd0 = pack2(g_bx[r0],     g_bx[r0]);
    const ull bxd1 = pack2(g_bx[r0 + 1], g_bx[r0 + 1]);
    const ull bxd2 = pack2(g_bx[r0 + 2], g_bx[r0 + 2]);
    const bool th0 = (r0     < NH);
    const bool th1 = (r0 + 1 < NH);
    const bool th2 = (r0 + 2 < NH);

    const ulonglong2* w0p = ws + (rg * 3) * K2;
    const ulonglong2* w1p = w0p + K2;
    const ulonglong2* w2p = w1p + K2;

    // output ull indices in interleaved layout for rows r0, r0+1, r0+2
    const int o0 = ((r0 >> 1) * 64 + pair) * 2 + (r0 & 1);
    const int o1 = (((r0 + 1) >> 1) * 64 + pair) * 2 + ((r0 + 1) & 1);
    const int o2 = (((r0 + 2) >> 1) * 64 + pair) * 2 + ((r0 + 2) & 1);

    __syncthreads();

    volatile unsigned* barp = &g_bar;

    for (int t = 0; t < TSTEPS; ++t) {
        const ulonglong2* zin  = g_z[t & 1] + pair;
        ull*              zout = (ull*)g_z[(t + 1) & 1];

        ull xx = *((const ull*)(x_in + (size_t)t * NB) + pair);
        ull a0 = fma2(bxd0, xx, 0ull);
        ull a1 = fma2(bxd1, xx, 0ull);
        ull a2 = fma2(bxd2, xx, 0ull);

        #pragma unroll 4
        for (int k2 = 0; k2 < K2; ++k2) {
            ulonglong2 z = ldcg2(zin + k2 * 64);   // {row 2k2, row 2k2+1}
            ulonglong2 w0 = w0p[k2];
            ulonglong2 w1 = w1p[k2];
            ulonglong2 w2 = w2p[k2];
            a0 = fma2(w0.x, z.x, a0); a0 = fma2(w0.y, z.y, a0);
            a1 = fma2(w1.x, z.x, a1); a1 = fma2(w1.y, z.y, a1);
            a2 = fma2(w2.x, z.x, a2); a2 = fma2(w2.y, z.y, a2);
        }

        float lo, hi;
        unpack2(a0, lo, hi);
        if (th0) { lo = tanhf(lo); hi = tanhf(hi); }
        zout[o0] = pack2(lo, hi);

        unpack2(a1, lo, hi);
        if (th1) { lo = tanhf(lo); hi = tanhf(hi); }
        zout[o1] = pack2(lo, hi);

        unpack2(a2, lo, hi);
        if (th2) { lo = tanhf(lo); hi = tanhf(hi); }
        zout[o2] = pack2(lo, hi);

        // grid barrier: release writes to L2, arrive, spin, then read fresh
        __threadfence();
        __syncthreads();
        if (tid == 0) {
            atomicAdd(&g_bar, 1u);
            unsigned target = (unsigned)(t + 1) * (unsigned)NCTA;
            while (*barp < target) __nanosleep(64);
        }
        __syncthreads();
        __threadfence();
    }
}

// ---- epilogue: logits + softmax, one warp per batch ------------------------
__global__ void dense_softmax(const float* __restrict__ Wd, const float* __restrict__ bd,
                              float* __restrict__ out) {
    int b = blockIdx.x;
    int l = threadIdx.x;
    float acc[10];
    #pragma unroll
    for (int o = 0; o < 10; ++o) acc[o] = 0.f;
    const ull* zf = (const ull*)g_z[0];   // final state: buf (783+1)&1 = 0
    for (int c = l; c < NH; c += 32) {
        ull v = zf[(((size_t)(c >> 1)) * 64 + (b >> 1)) * 2 + (c & 1)];
        float lo, hi;
        unpack2(v, lo, hi);
        float hv = (b & 1) ? hi : lo;
        #pragma unroll
        for (int o = 0; o < 10; ++o) acc[o] = fmaf(hv, Wd[o * NH + c], acc[o]);
    }
    #pragma unroll
    for (int o = 0; o < 10; ++o)
        for (int s = 16; s; s >>= 1) acc[o] += __shfl_xor_sync(0xffffffffu, acc[o], s);
    if (l == 0) {
        float mx = -1e30f;
        #pragma unroll
        for (int o = 0; o < 10; ++o) { acc[o] += bd[o]; mx = fmaxf(mx, acc[o]); }
        float s = 0.f;
        #pragma unroll
        for (int o = 0; o < 10; ++o) { acc[o] = expf(acc[o] - mx); s += acc[o]; }
        float inv = 1.f / s;
        #pragma unroll
        for (int o = 0; o < 10; ++o) out[b * 10 + o] = acc[o] * inv;
    }
}

// ---------------------------------------------------------------------------
extern "C" void kernel_launch(void* const* d_in, const int* in_sizes, int n_in,
                              void* d_out, int out_size) {
    (void)in_sizes; (void)n_in; (void)out_size;
    const float* inputs = (const float*)d_in[0];
    const float* e_x    = (const float*)d_in[1];
    const float* e_h    = (const float*)d_in[2];
    const float* e_m    = (const float*)d_in[3];
    const float* W_x    = (const float*)d_in[4];
    const float* W_h    = (const float*)d_in[5];
    const float* W_m    = (const float*)d_in[6];
    const float* AT     = (const float*)d_in[7];
    const float* BT     = (const float*)d_in[8];
    const float* Wd     = (const float*)d_in[9];
    const float* bd     = (const float*)d_in[10];

    cudaFuncSetAttribute(lmu_main, cudaFuncAttributeMaxDynamicSharedMemorySize, SMEMB);

    prepInit<<<768, 256>>>();                       // NZ*NB threads
    prepA<<<6, 256>>>(W_m, BT, W_x, e_x);           // 1536 threads
    prepHm<<<2048, 256>>>(W_m, AT, e_m);            // 1024*512 threads
    prepRest<<<2048, 256>>>(W_h, AT, BT, e_h, e_m); // grid-stride NZ*NZ
    lmu_main<<<NCTA, 256, SMEMB>>>(inputs);
    dense_softmax<<<NB, 32>>>(Wd, bd, (float*)d_out);
}

// round 12
// speedup vs baseline: 1.4612x; 1.4612x over previous
#include <cuda_runtime.h>
#include <math.h>

// ---------------------------------------------------------------------------
// LMU: folded single-GEMM persistent recurrence, fp32 with f32x2 FMA.
//   z = [h(1024); m(512)], per step: z' = act( Wbig @ z + x_t * bx ),
//   tanh on rows < 1024.  Wbig/bx precomputed on-device each launch.
//   R12 change vs R11: z loads use ld.global.ca (L1-cached) instead of .cg —
//   the 4 row-group warps per SM reuse each z line 4x; L1 serves the reuse
//   (CCTL.IVALL from the per-step __threadfence keeps it coherent), cutting
//   L2 traffic from 403 MB/step to ~100 MB/step. Unroll 4 -> 8 for MLP.
// ---------------------------------------------------------------------------

#define NZ     1536
#define NH     1024
#define NO     512
#define NB     128
#define TSTEPS 784
#define NCTA   128
#define RPC    12           // rows per CTA
#define K2     768          // NZ/2 (row pairs)
#define SMEMB  (RPC * K2 * 16)   // 147456 B: dup'd f32x2 weight pairs

typedef unsigned long long ull;

__device__ float      g_W[NZ * NZ];        // folded Wbig, row-major
__device__ float      g_bx[NZ];
__device__ float      g_wmb[NH];
__device__ ulonglong2 g_z[2][K2 * 64];     // ping-pong state, interleaved
__device__ unsigned   g_bar;               // monotonic grid-barrier counter

// ---- packed fp32x2 helpers -------------------------------------------------
__device__ __forceinline__ ull pack2(float a, float b) {
    ull d; unsigned x = __float_as_uint(a), y = __float_as_uint(b);
    asm("mov.b64 %0, {%1, %2};" : "=l"(d) : "r"(x), "r"(y));
    return d;
}
__device__ __forceinline__ void unpack2(ull v, float& a, float& b) {
    unsigned x, y;
    asm("mov.b64 {%0, %1}, %2;" : "=r"(x), "=r"(y) : "l"(v));
    a = __uint_as_float(x); b = __uint_as_float(y);
}
__device__ __forceinline__ ull fma2(ull a, ull b, ull c) {
    ull d;
    asm("fma.rn.f32x2 %0, %1, %2, %3;" : "=l"(d) : "l"(a), "l"(b), "l"(c));
    return d;
}
// L1-cached 128-bit z load. Safe across steps: the post-barrier
// __threadfence() emits CCTL.IVALL (gpu-scope fence flushes L1D on sm_103a).
__device__ __forceinline__ ulonglong2 ldca2(const ulonglong2* p) {
    ulonglong2 v;
    asm volatile("ld.global.ca.v2.u64 {%0,%1}, [%2];"
                 : "=l"(v.x), "=l"(v.y) : "l"(p));
    return v;
}

// ---- prep: wmb = W_m@BT, bias bx -------------------------------------------
__global__ void prepA(const float* __restrict__ W_m, const float* __restrict__ BT,
                      const float* __restrict__ W_x, const float* __restrict__ e_x) {
    int i = blockIdx.x * blockDim.x + threadIdx.x;
    float ex = e_x[0];
    if (i < NH) {
        float s = 0.f;
        for (int j = 0; j < NO; ++j) s = fmaf(W_m[i * NO + j], BT[j], s);
        g_wmb[i] = s;
        g_bx[i]  = W_x[i] + s * ex;
    } else if (i < NZ) {
        g_bx[i] = BT[i - NH] * ex;
    }
}

// ---- prep: Hm block  g_W[i][1024+k] = (W_m@AT)[i,k] + W_m[i,k] + wmb[i]e_m[k]
__global__ void prepHm(const float* __restrict__ W_m, const float* __restrict__ AT,
                       const float* __restrict__ e_m) {
    int id = blockIdx.x * blockDim.x + threadIdx.x;   // 1024*512 threads exactly
    int i = id >> 9, k = id & 511;
    float s = 0.f;
    for (int j = 0; j < NO; ++j) s = fmaf(W_m[i * NO + j], AT[j * NO + k], s);
    g_W[i * NZ + NH + k] = s + W_m[i * NO + k] + g_wmb[i] * e_m[k];
}

// ---- prep: Hh, Mh, Mm blocks ------------------------------------------------
__global__ void prepRest(const float* __restrict__ W_h, const float* __restrict__ AT,
                         const float* __restrict__ BT, const float* __restrict__ e_h,
                         const float* __restrict__ e_m) {
    for (int id = blockIdx.x * blockDim.x + threadIdx.x; id < NZ * NZ;
         id += gridDim.x * blockDim.x) {
        int r = id / NZ, c = id - r * NZ;
        if (r < NH) {
            if (c < NH) g_W[id] = W_h[r * NH + c] + g_wmb[r] * e_h[c];
            // c >= NH written by prepHm
        } else {
            int j = r - NH;
            if (c < NH) {
                g_W[id] = BT[j] * e_h[c];
            } else {
                int k = c - NH;
                g_W[id] = ((j == k) ? 1.0f : 0.0f) + AT[j * NO + k] + BT[j] * e_m[k];
            }
        }
    }
}

// ---- prep: zero initial state + barrier counter ----------------------------
__global__ void prepInit() {
    int id = blockIdx.x * blockDim.x + threadIdx.x;   // 768*256 = NZ*NB exactly
    ((float*)g_z[0])[id] = 0.0f;
    if (id == 0) g_bar = 0u;
}

// ---- main persistent recurrence --------------------------------------------
// 128 CTAs x 256 thr, 1 CTA/SM (147KB smem => occ 1; all co-resident, so the
// monotonic-counter grid barrier is deadlock-free). CTA owns rows [cta*12,+12).
// Thread: 3 rows x 2 batches. Weights dup'd in SMEM; z in L2, reused via L1.
__global__ void __launch_bounds__(256, 1) lmu_main(const float* __restrict__ x_in) {
    extern __shared__ ulonglong2 ws[];   // ws[r*K2+k2] = {dup(w[r][2k2]), dup(w[r][2k2+1])}
    const int tid = threadIdx.x;
    const int cta = blockIdx.x;
    const int R0  = cta * RPC;

    // stage + duplicate this CTA's weight slice
    const float2* gw2 = (const float2*)g_W;
    for (int idx = tid; idx < RPC * K2; idx += 256) {
        int r = idx / K2, k2 = idx - r * K2;
        float2 w = gw2[(size_t)(R0 + r) * K2 + k2];
        ulonglong2 v;
        v.x = pack2(w.x, w.x);
        v.y = pack2(w.y, w.y);
        ws[idx] = v;
    }

    const int pair = tid & 63;           // batches 2*pair, 2*pair+1
    const int rg   = tid >> 6;           // 0..3, uniform within each warp
    const int r0   = R0 + rg * 3;

    const ull bxd0 = pack2(g_bx[r0],     g_bx[r0]);
    const ull bxd1 = pack2(g_bx[r0 + 1], g_bx[r0 + 1]);
    const ull bxd2 = pack2(g_bx[r0 + 2], g_bx[r0 + 2]);
    const bool th0 = (r0     < NH);
    const bool th1 = (r0 + 1 < NH);
    const bool th2 = (r0 + 2 < NH);

    const ulonglong2* w0p = ws + (rg * 3) * K2;
    const ulonglong2* w1p = w0p + K2;
    const ulonglong2* w2p = w1p + K2;

    // output ull indices in interleaved layout for rows r0, r0+1, r0+2
    const int o0 = ((r0 >> 1) * 64 + pair) * 2 + (r0 & 1);
    const int o1 = (((r0 + 1) >> 1) * 64 + pair) * 2 + ((r0 + 1) & 1);
    const int o2 = (((r0 + 2) >> 1) * 64 + pair) * 2 + ((r0 + 2) & 1);

    __syncthreads();

    volatile unsigned* barp = &g_bar;

    for (int t = 0; t < TSTEPS; ++t) {
        const ulonglong2* zin  = g_z[t & 1] + pair;
        ull*              zout = (ull*)g_z[(t + 1) & 1];

        ull xx = *((const ull*)(x_in + (size_t)t * NB) + pair);
        ull a0 = fma2(bxd0, xx, 0ull);
        ull a1 = fma2(bxd1, xx, 0ull);
        ull a2 = fma2(bxd2, xx, 0ull);

        #pragma unroll 8
        for (int k2 = 0; k2 < K2; ++k2) {
            ulonglong2 z = ldca2(zin + k2 * 64);   // {row 2k2, row 2k2+1} x 2 batches
            ulonglong2 w0 = w0p[k2];
            ulonglong2 w1 = w1p[k2];
            ulonglong2 w2 = w2p[k2];
            a0 = fma2(w0.x, z.x, a0); a0 = fma2(w0.y, z.y, a0);
            a1 = fma2(w1.x, z.x, a1); a1 = fma2(w1.y, z.y, a1);
            a2 = fma2(w2.x, z.x, a2); a2 = fma2(w2.y, z.y, a2);
        }

        float lo, hi;
        unpack2(a0, lo, hi);
        if (th0) { lo = tanhf(lo); hi = tanhf(hi); }
        zout[o0] = pack2(lo, hi);

        unpack2(a1, lo, hi);
        if (th1) { lo = tanhf(lo); hi = tanhf(hi); }
        zout[o1] = pack2(lo, hi);

        unpack2(a2, lo, hi);
        if (th2) { lo = tanhf(lo); hi = tanhf(hi); }
        zout[o2] = pack2(lo, hi);

        // grid barrier: release writes to L2, arrive, spin, then invalidate L1
        __threadfence();
        __syncthreads();
        if (tid == 0) {
            atomicAdd(&g_bar, 1u);
            unsigned target = (unsigned)(t + 1) * (unsigned)NCTA;
            while (*barp < target) __nanosleep(64);
        }
        __syncthreads();
        __threadfence();                 // CCTL.IVALL: fresh z reads next step
    }
}

// ---- epilogue: logits + softmax, one warp per batch ------------------------
__global__ void dense_softmax(const float* __restrict__ Wd, const float* __restrict__ bd,
                              float* __restrict__ out) {
    int b = blockIdx.x;
    int l = threadIdx.x;
    float acc[10];
    #pragma unroll
    for (int o = 0; o < 10; ++o) acc[o] = 0.f;
    const ull* zf = (const ull*)g_z[0];   // final state: buf (783+1)&1 = 0
    for (int c = l; c < NH; c += 32) {
        ull v = zf[(((size_t)(c >> 1)) * 64 + (b >> 1)) * 2 + (c & 1)];
        float lo, hi;
        unpack2(v, lo, hi);
        float hv = (b & 1) ? hi : lo;
        #pragma unroll
        for (int o = 0; o < 10; ++o) acc[o] = fmaf(hv, Wd[o * NH + c], acc[o]);
    }
    #pragma unroll
    for (int o = 0; o < 10; ++o)
        for (int s = 16; s; s >>= 1) acc[o] += __shfl_xor_sync(0xffffffffu, acc[o], s);
    if (l == 0) {
        float mx = -1e30f;
        #pragma unroll
        for (int o = 0; o < 10; ++o) { acc[o] += bd[o]; mx = fmaxf(mx, acc[o]); }
        float s = 0.f;
        #pragma unroll
        for (int o = 0; o < 10; ++o) { acc[o] = expf(acc[o] - mx); s += acc[o]; }
        float inv = 1.f / s;
        #pragma unroll
        for (int o = 0; o < 10; ++o) out[b * 10 + o] = acc[o] * inv;
    }
}

// ---------------------------------------------------------------------------
extern "C" void kernel_launch(void* const* d_in, const int* in_sizes, int n_in,
                              void* d_out, int out_size) {
    (void)in_sizes; (void)n_in; (void)out_size;
    const float* inputs = (const float*)d_in[0];
    const float* e_x    = (const float*)d_in[1];
    const float* e_h    = (const float*)d_in[2];
    const float* e_m    = (const float*)d_in[3];
    const float* W_x    = (const float*)d_in[4];
    const float* W_h    = (const float*)d_in[5];
    const float* W_m    = (const float*)d_in[6];
    const float* AT     = (const float*)d_in[7];
    const float* BT     = (const float*)d_in[8];
    const float* Wd     = (const float*)d_in[9];
    const float* bd     = (const float*)d_in[10];

    cudaFuncSetAttribute(lmu_main, cudaFuncAttributeMaxDynamicSharedMemorySize, SMEMB);

    prepInit<<<768, 256>>>();                       // NZ*NB threads
    prepA<<<6, 256>>>(W_m, BT, W_x, e_x);           // 1536 threads
    prepHm<<<2048, 256>>>(W_m, AT, e_m);            // 1024*512 threads
    prepRest<<<2048, 256>>>(W_h, AT, BT, e_h, e_m); // grid-stride NZ*NZ
    lmu_main<<<NCTA, 256, SMEMB>>>(inputs);
    dense_softmax<<<NB, 32>>>(Wd, bd, (float*)d_out);
}

// round 15
// speedup vs baseline: 2.4125x; 1.6511x over previous
#include <cuda_runtime.h>
#include <math.h>

// ---------------------------------------------------------------------------
// LMU: folded single-GEMM persistent recurrence, fp32 with f32x2 FMA.
//   z = [h(1024); m(512)], per step: z' = act( Wbig @ z + x_t * bx ),
//   tanh on rows < 1024.  Wbig/bx precomputed on-device each launch.
//
//   K-SPLIT mapping: thread (rg, pair) accumulates ALL 12 CTA rows x 2
//   batches over k-quarter rg (192 of 768 k2-pairs), so each z line is loaded
//   exactly ONCE per SM. Partials reduced through 24.6 KB SMEM; bias + tanh
//   applied in the reduction phase. z loads .cg (no intra-SM reuse exists).
// ---------------------------------------------------------------------------

#define NZ     1536
#define NH     1024
#define NO     512
#define NB     128
#define TSTEPS 784
#define NCTA   128
#define RPC    12            // rows per CTA
#define K2     768           // NZ/2 (row pairs along k)
#define KQ     192           // k2 per k-quarter (K2/4)
#define WSB    (RPC * K2 * 16)        // 147456 B dup'd weight pairs
#define REDB   (4 * RPC * 64 * 8)     // 24576 B partial sums
#define SMEMB  (WSB + REDB)           // 172032 B dynamic SMEM

typedef unsigned long long ull;

__device__ float      g_W[NZ * NZ];        // folded Wbig, row-major
__device__ float      g_bx[NZ];
__device__ float      g_wmb[NH];
__device__ ulonglong2 g_z[2][K2 * 64];     // ping-pong state, interleaved
__device__ unsigned   g_bar;               // monotonic grid-barrier counter

// ---- packed fp32x2 helpers -------------------------------------------------
__device__ __forceinline__ ull pack2(float a, float b) {
    ull d; unsigned x = __float_as_uint(a), y = __float_as_uint(b);
    asm("mov.b64 %0, {%1, %2};" : "=l"(d) : "r"(x), "r"(y));
    return d;
}
__device__ __forceinline__ void unpack2(ull v, float& a, float& b) {
    unsigned x, y;
    asm("mov.b64 {%0, %1}, %2;" : "=r"(x), "=r"(y) : "l"(v));
    a = __uint_as_float(x); b = __uint_as_float(y);
}
__device__ __forceinline__ ull fma2(ull a, ull b, ull c) {
    ull d;
    asm("fma.rn.f32x2 %0, %1, %2, %3;" : "=l"(d) : "l"(a), "l"(b), "l"(c));
    return d;
}
__device__ __forceinline__ ull add2(ull a, ull b) {
    ull d;
    asm("add.rn.f32x2 %0, %1, %2;" : "=l"(d) : "l"(a), "l"(b));
    return d;
}
__device__ __forceinline__ ulonglong2 ldcg2(const ulonglong2* p) {
    ulonglong2 v;
    asm volatile("ld.global.cg.v2.u64 {%0,%1}, [%2];"
                 : "=l"(v.x), "=l"(v.y) : "l"(p));
    return v;
}

// ---- prep: wmb = W_m@BT, bias bx -------------------------------------------
__global__ void prepA(const float* __restrict__ W_m, const float* __restrict__ BT,
                      const float* __restrict__ W_x, const float* __restrict__ e_x) {
    int i = blockIdx.x * blockDim.x + threadIdx.x;
    float ex = e_x[0];
    if (i < NH) {
        float s = 0.f;
        for (int j = 0; j < NO; ++j) s = fmaf(W_m[i * NO + j], BT[j], s);
        g_wmb[i] = s;
        g_bx[i]  = W_x[i] + s * ex;
    } else if (i < NZ) {
        g_bx[i] = BT[i - NH] * ex;
    }
}

// ---- prep: Hm block  g_W[i][1024+k] = (W_m@AT)[i,k] + W_m[i,k] + wmb[i]e_m[k]
__global__ void prepHm(const float* __restrict__ W_m, const float* __restrict__ AT,
                       const float* __restrict__ e_m) {
    int id = blockIdx.x * blockDim.x + threadIdx.x;   // 1024*512 threads exactly
    int i = id >> 9, k = id & 511;
    float s = 0.f;
    for (int j = 0; j < NO; ++j) s = fmaf(W_m[i * NO + j], AT[j * NO + k], s);
    g_W[i * NZ + NH + k] = s + W_m[i * NO + k] + g_wmb[i] * e_m[k];
}

// ---- prep: Hh, Mh, Mm blocks ------------------------------------------------
__global__ void prepRest(const float* __restrict__ W_h, const float* __restrict__ AT,
                         const float* __restrict__ BT, const float* __restrict__ e_h,
                         const float* __restrict__ e_m) {
    for (int id = blockIdx.x * blockDim.x + threadIdx.x; id < NZ * NZ;
         id += gridDim.x * blockDim.x) {
        int r = id / NZ, c = id - r * NZ;
        if (r < NH) {
            if (c < NH) g_W[id] = W_h[r * NH + c] + g_wmb[r] * e_h[c];
            // c >= NH written by prepHm
        } else {
            int j = r - NH;
            if (c < NH) {
                g_W[id] = BT[j] * e_h[c];
            } else {
                int k = c - NH;
                g_W[id] = ((j == k) ? 1.0f : 0.0f) + AT[j * NO + k] + BT[j] * e_m[k];
            }
        }
    }
}

// ---- prep: zero initial state + barrier counter ----------------------------
__global__ void prepInit() {
    int id = blockIdx.x * blockDim.x + threadIdx.x;   // 768*256 = NZ*NB exactly
    ((float*)g_z[0])[id] = 0.0f;
    if (id == 0) g_bar = 0u;
}

// ---- main persistent recurrence --------------------------------------------
// 128 CTAs x 256 thr, 1 CTA/SM (172KB smem => occ 1; all co-resident, so the
// monotonic-counter grid barrier is deadlock-free). CTA owns rows [cta*12,+12).
// Thread (rg = tid>>6, pair = tid&63): ALL 12 rows x 2 batches over k-quarter
// rg. Partials reduced via SMEM; bias + tanh in the reduction phase.
__global__ void __launch_bounds__(256, 1) lmu_main(const float* __restrict__ x_in) {
    extern __shared__ char smem_raw[];
    ulonglong2* ws  = (ulonglong2*)smem_raw;           // [row*K2 + k2] dup'd pairs
    ull*        red = (ull*)(smem_raw + WSB);          // [(rg*12+row)*64 + pair]

    const int tid = threadIdx.x;
    const int cta = blockIdx.x;
    const int R0  = cta * RPC;

    // stage + duplicate this CTA's weight slice
    const float2* gw2 = (const float2*)g_W;
    for (int idx = tid; idx < RPC * K2; idx += 256) {
        int r = idx / K2, k2 = idx - r * K2;
        float2 w = gw2[(size_t)(R0 + r) * K2 + k2];
        ulonglong2 v;
        v.x = pack2(w.x, w.x);
        v.y = pack2(w.y, w.y);
        ws[idx] = v;
    }

    const int pair = tid & 63;           // batches 2*pair, 2*pair+1
    const int rg   = tid >> 6;           // k-quarter 0..3 (uniform per warp)
    const int k2b  = rg * KQ;

    // reduction-phase constants: this thread reduces rows rr0..rr0+2
    const int rr0 = rg * 3;              // local row base for reduce
    const int gr0 = R0 + rr0;
    const ull bxd0 = pack2(g_bx[gr0],     g_bx[gr0]);
    const ull bxd1 = pack2(g_bx[gr0 + 1], g_bx[gr0 + 1]);
    const ull bxd2 = pack2(g_bx[gr0 + 2], g_bx[gr0 + 2]);
    const bool th0 = (gr0     < NH);
    const bool th1 = (gr0 + 1 < NH);
    const bool th2 = (gr0 + 2 < NH);
    const int o0 = ((gr0 >> 1) * 64 + pair) * 2 + (gr0 & 1);
    const int o1 = (((gr0 + 1) >> 1) * 64 + pair) * 2 + ((gr0 + 1) & 1);
    const int o2 = (((gr0 + 2) >> 1) * 64 + pair) * 2 + ((gr0 + 2) & 1);

    const ulonglong2* wsq = ws + k2b;    // weight base for this k-quarter

    __syncthreads();

    volatile unsigned* barp = &g_bar;

    for (int t = 0; t < TSTEPS; ++t) {
        const ulonglong2* zin  = g_z[t & 1] + (size_t)k2b * 64 + pair;
        ull*              zout = (ull*)g_z[(t + 1) & 1];

        ull acc[RPC];
        #pragma unroll
        for (int r = 0; r < RPC; ++r) acc[r] = 0ull;

        #pragma unroll 4
        for (int k2 = 0; k2 < KQ; ++k2) {
            ulonglong2 z = ldcg2(zin + k2 * 64);   // {row 2k2, 2k2+1} x 2 batches
            #pragma unroll
            for (int r = 0; r < RPC; ++r) {
                ulonglong2 w = wsq[r * K2 + k2];   // uniform addr -> LDS broadcast
                acc[r] = fma2(w.x, z.x, acc[r]);
                acc[r] = fma2(w.y, z.y, acc[r]);
            }
        }

        // publish partials
        #pragma unroll
        for (int r = 0; r < RPC; ++r)
            red[(rg * RPC + r) * 64 + pair] = acc[r];
        __syncthreads();

        // reduce 4 partials for my 3 rows, add x-bias, activate, store z'
        ull xx = *((const ull*)(x_in + (size_t)t * NB) + pair);
        #pragma unroll
        for (int j = 0; j < 3; ++j) {
            int rr = rr0 + j;
            ull s = add2(add2(red[(0 * RPC + rr) * 64 + pair],
                              red[(1 * RPC + rr) * 64 + pair]),
                         add2(red[(2 * RPC + rr) * 64 + pair],
                              red[(3 * RPC + rr) * 64 + pair]));
            ull bxd = (j == 0) ? bxd0 : (j == 1) ? bxd1 : bxd2;
            s = fma2(bxd, xx, s);
            float lo, hi;
            unpack2(s, lo, hi);
            bool th = (j == 0) ? th0 : (j == 1) ? th1 : th2;
            if (th) { lo = tanhf(lo); hi = tanhf(hi); }
            int o = (j == 0) ? o0 : (j == 1) ? o1 : o2;
            zout[o] = pack2(lo, hi);
        }

        // grid barrier: release writes to L2, arrive, spin
        __threadfence();
        __syncthreads();
        if (tid == 0) {
            atomicAdd(&g_bar, 1u);
            unsigned target = (unsigned)(t + 1) * (unsigned)NCTA;
            while (*barp < target) __nanosleep(64);
        }
        __syncthreads();
    }
}

// ---- epilogue: logits + softmax, one warp per batch ------------------------
__global__ void dense_softmax(const float* __restrict__ Wd, const float* __restrict__ bd,
                              float* __restrict__ out) {
    int b = blockIdx.x;
    int l = threadIdx.x;
    float acc[10];
    #pragma unroll
    for (int o = 0; o < 10; ++o) acc[o] = 0.f;
    const ull* zf = (const ull*)g_z[0];   // final state: buf (783+1)&1 = 0
    for (int c = l; c < NH; c += 32) {
        ull v = zf[(((size_t)(c >> 1)) * 64 + (b >> 1)) * 2 + (c & 1)];
        float lo, hi;
        unpack2(v, lo, hi);
        float hv = (b & 1) ? hi : lo;
        #pragma unroll
        for (int o = 0; o < 10; ++o) acc[o] = fmaf(hv, Wd[o * NH + c], acc[o]);
    }
    #pragma unroll
    for (int o = 0; o < 10; ++o)
        for (int s = 16; s; s >>= 1) acc[o] += __shfl_xor_sync(0xffffffffu, acc[o], s);
    if (l == 0) {
        float mx = -1e30f;
        #pragma unroll
        for (int o = 0; o < 10; ++o) { acc[o] += bd[o]; mx = fmaxf(mx, acc[o]); }
        float s = 0.f;
        #pragma unroll
        for (int o = 0; o < 10; ++o) { acc[o] = expf(acc[o] - mx); s += acc[o]; }
        float inv = 1.f / s;
        #pragma unroll
        for (int o = 0; o < 10; ++o) out[b * 10 + o] = acc[o] * inv;
    }
}

// ---------------------------------------------------------------------------
extern "C" void kernel_launch(void* const* d_in, const int* in_sizes, int n_in,
                              void* d_out, int out_size) {
    (void)in_sizes; (void)n_in; (void)out_size;
    const float* inputs = (const float*)d_in[0];
    const float* e_x    = (const float*)d_in[1];
    const float* e_h    = (const float*)d_in[2];
    const float* e_m    = (const float*)d_in[3];
    const float* W_x    = (const float*)d_in[4];
    const float* W_h    = (const float*)d_in[5];
    const float* W_m    = (const float*)d_in[6];
    const float* AT     = (const float*)d_in[7];
    const float* BT     = (const float*)d_in[8];
    const float* Wd     = (const float*)d_in[9];
    const float* bd     = (const float*)d_in[10];

    cudaFuncSetAttribute(lmu_main, cudaFuncAttributeMaxDynamicSharedMemorySize, SMEMB);

    prepInit<<<768, 256>>>();                       // NZ*NB threads
    prepA<<<6, 256>>>(W_m, BT, W_x, e_x);           // 1536 threads
    prepHm<<<2048, 256>>>(W_m, AT, e_m);            // 1024*512 threads
    prepRest<<<2048, 256>>>(W_h, AT, BT, e_h, e_m); // grid-stride NZ*NZ
    lmu_main<<<NCTA, 256, SMEMB>>>(inputs);
    dense_softmax<<<NB, 32>>>(Wd, bd, (float*)d_out);
}